// round 9
// baseline (speedup 1.0000x reference)
#include <cuda_runtime.h>
#include <cuda_bf16.h>
#include <cstdint>
#include <math.h>

#define B_   2
#define H_   16
#define N_   2048
#define D_   64
#define C_   1024
#define BH_  (B_*H_)

// Scratch (device globals: allocation-free rule)
__device__ float g_q[BH_*N_*D_];    // [b*h][n][64], pre-scaled by log2e/32
__device__ float g_k[BH_*N_*D_];
__device__ float g_v[BH_*N_*D_];
__device__ float g_ao[B_*N_*C_];    // attention output, [b][n][h*64+d]

// ---- packed f32x2 helpers ----
typedef unsigned long long ull;

__device__ __forceinline__ ull dup2(float x) {
    ull d; asm("mov.b64 %0, {%1, %1};" : "=l"(d) : "f"(x)); return d;
}
__device__ __forceinline__ void upk2(ull d, float& x, float& y) {
    asm("mov.b64 {%0, %1}, %2;" : "=f"(x), "=f"(y) : "l"(d));
}
__device__ __forceinline__ void fma2(ull& d, ull a, ull b) {
    asm("fma.rn.f32x2 %0, %1, %2, %0;" : "+l"(d) : "l"(a), "l"(b));
}
__device__ __forceinline__ void mul2(ull& d, ull a) {
    asm("mul.rn.f32x2 %0, %0, %1;" : "+l"(d) : "l"(a));
}
__device__ __forceinline__ void add2(ull& d, ull a) {
    asm("add.rn.f32x2 %0, %0, %1;" : "+l"(d) : "l"(a));
}

// ===========================================================================
// GEMM 128x128, 128 threads, 16x8 micro, KST=16 double-buffer, A duplicated
// in smem so the broadcast operand is a direct LDS.64 (no dup2 MOVs).
// smem: AsD 2*16*256 floats (32KB) + Bs 2*16*128 (16KB) = 48KB static.
// ===========================================================================
#define KST 16

__global__ void __launch_bounds__(128) gemm_qkv(const float* __restrict__ X,
                                                const float* __restrict__ W) {
    __shared__ float AsD[2*KST*256];
    __shared__ float Bs[2*KST*128];
    const int t  = threadIdx.x;
    const int cx = t & 15;        // col group 0..15
    const int ry = t >> 4;        // row group 0..7
    const int bn = blockIdx.x;    // 0..23
    const int bm = blockIdx.y;    // 0..31

    const int kB = t >> 3, colB = (t & 7) * 16;

    const float* Ap = X + (size_t)(bm*128 + t) * C_;
    const float* Bp = W + (size_t)kB * 3072 + bn*128 + colB;

    float4 pa[4], pb[4];
    #pragma unroll
    for (int g = 0; g < 4; g++) pa[g] = *(const float4*)(Ap + g*4);
    #pragma unroll
    for (int g = 0; g < 4; g++) pb[g] = *(const float4*)(Bp + g*4);

    auto sts = [&](int s) {
        float* as = &AsD[s*KST*256];
        float* bs = &Bs[s*KST*128];
        #pragma unroll
        for (int g = 0; g < 4; g++) {
            float v0 = pa[g].x, v1 = pa[g].y, v2 = pa[g].z, v3 = pa[g].w;
            *(float2*)&as[(g*4+0)*256 + 2*t] = make_float2(v0, v0);
            *(float2*)&as[(g*4+1)*256 + 2*t] = make_float2(v1, v1);
            *(float2*)&as[(g*4+2)*256 + 2*t] = make_float2(v2, v2);
            *(float2*)&as[(g*4+3)*256 + 2*t] = make_float2(v3, v3);
            *(float4*)&bs[kB*128 + colB + g*4] = pb[g];
        }
    };

    sts(0);
    __syncthreads();

    ull acc2[16][4] = {};

    const int NST = C_ / KST;   // 64
    for (int j = 0; j < NST; j++) {
        const int s = j & 1;
        if (j + 1 < NST) {
            Ap += KST; Bp += (size_t)KST * 3072;
            #pragma unroll
            for (int g = 0; g < 4; g++) pa[g] = *(const float4*)(Ap + g*4);
            #pragma unroll
            for (int g = 0; g < 4; g++) pb[g] = *(const float4*)(Bp + g*4);
        }
        const float* as = &AsD[s*KST*256];
        const float* bs = &Bs[s*KST*128];
        #pragma unroll
        for (int kk = 0; kk < KST; kk++) {
            ulonglong2 bq0 = *(const ulonglong2*)&bs[kk*128 + cx*4];
            ulonglong2 bq1 = *(const ulonglong2*)&bs[kk*128 + 64 + cx*4];
            #pragma unroll
            for (int u = 0; u < 4; u++)
                #pragma unroll
                for (int i = 0; i < 4; i++) {
                    ull ap = *(const ull*)&as[kk*256 + 2*(32*u + ry*4 + i)];
                    fma2(acc2[u*4+i][0], ap, bq0.x);
                    fma2(acc2[u*4+i][1], ap, bq0.y);
                    fma2(acc2[u*4+i][2], ap, bq1.x);
                    fma2(acc2[u*4+i][3], ap, bq1.y);
                }
        }
        if (j + 1 < NST) { sts(s ^ 1); __syncthreads(); }
    }

    // Epilogue: scatter to q/k/v. Q scaled by (1/32)*log2(e) so attn can exp2.
    #pragma unroll
    for (int u = 0; u < 4; u++)
        #pragma unroll
        for (int i = 0; i < 4; i++) {
            const int r16 = u*4 + i;
            const int m  = bm*128 + 32*u + ry*4 + i;
            const int bb = m >> 11, nr = m & 2047;
            #pragma unroll
            for (int hc = 0; hc < 2; hc++) {
                const int nn = bn*128 + hc*64 + cx*4;
                const int sel = nn >> 10;
                const int w = nn & 1023, h = w >> 6, d = w & 63;
                float* dst = (sel == 0) ? g_q : (sel == 1) ? g_k : g_v;
                const ull scp = dup2((sel == 0) ? 0.03125f * 1.4426950408889634f : 1.0f);
                ull e0 = acc2[r16][hc*2+0], e1 = acc2[r16][hc*2+1];
                mul2(e0, scp); mul2(e1, scp);
                ulonglong2 o; o.x = e0; o.y = e1;
                *(ulonglong2*)&dst[(((size_t)(bb*H_ + h))*N_ + nr)*D_ + d] = o;
            }
        }
}

__global__ void __launch_bounds__(128) gemm_out(const float* __restrict__ W,
                                                const float* __restrict__ bias,
                                                float* __restrict__ out) {
    __shared__ float AsD[2*KST*256];
    __shared__ float Bs[2*KST*128];
    const int t  = threadIdx.x;
    const int cx = t & 15;
    const int ry = t >> 4;
    const int bn = blockIdx.x;    // 0..7
    const int bm = blockIdx.y;    // 0..31

    const int kB = t >> 3, colB = (t & 7) * 16;

    const float* Ap = g_ao + (size_t)(bm*128 + t) * C_;
    const float* Bp = W + (size_t)kB * C_ + bn*128 + colB;

    float4 pa[4], pb[4];
    #pragma unroll
    for (int g = 0; g < 4; g++) pa[g] = *(const float4*)(Ap + g*4);
    #pragma unroll
    for (int g = 0; g < 4; g++) pb[g] = *(const float4*)(Bp + g*4);

    auto sts = [&](int s) {
        float* as = &AsD[s*KST*256];
        float* bs = &Bs[s*KST*128];
        #pragma unroll
        for (int g = 0; g < 4; g++) {
            float v0 = pa[g].x, v1 = pa[g].y, v2 = pa[g].z, v3 = pa[g].w;
            *(float2*)&as[(g*4+0)*256 + 2*t] = make_float2(v0, v0);
            *(float2*)&as[(g*4+1)*256 + 2*t] = make_float2(v1, v1);
            *(float2*)&as[(g*4+2)*256 + 2*t] = make_float2(v2, v2);
            *(float2*)&as[(g*4+3)*256 + 2*t] = make_float2(v3, v3);
            *(float4*)&bs[kB*128 + colB + g*4] = pb[g];
        }
    };

    sts(0);
    __syncthreads();

    ull acc2[16][4] = {};

    const int NST = C_ / KST;   // 64
    for (int j = 0; j < NST; j++) {
        const int s = j & 1;
        if (j + 1 < NST) {
            Ap += KST; Bp += (size_t)KST * C_;
            #pragma unroll
            for (int g = 0; g < 4; g++) pa[g] = *(const float4*)(Ap + g*4);
            #pragma unroll
            for (int g = 0; g < 4; g++) pb[g] = *(const float4*)(Bp + g*4);
        }
        const float* as = &AsD[s*KST*256];
        const float* bs = &Bs[s*KST*128];
        #pragma unroll
        for (int kk = 0; kk < KST; kk++) {
            ulonglong2 bq0 = *(const ulonglong2*)&bs[kk*128 + cx*4];
            ulonglong2 bq1 = *(const ulonglong2*)&bs[kk*128 + 64 + cx*4];
            #pragma unroll
            for (int u = 0; u < 4; u++)
                #pragma unroll
                for (int i = 0; i < 4; i++) {
                    ull ap = *(const ull*)&as[kk*256 + 2*(32*u + ry*4 + i)];
                    fma2(acc2[u*4+i][0], ap, bq0.x);
                    fma2(acc2[u*4+i][1], ap, bq0.y);
                    fma2(acc2[u*4+i][2], ap, bq1.x);
                    fma2(acc2[u*4+i][3], ap, bq1.y);
                }
        }
        if (j + 1 < NST) { sts(s ^ 1); __syncthreads(); }
    }

    #pragma unroll
    for (int u = 0; u < 4; u++)
        #pragma unroll
        for (int i = 0; i < 4; i++) {
            const int r16 = u*4 + i;
            const size_t m = (size_t)(bm*128 + 32*u + ry*4 + i);
            #pragma unroll
            for (int hc = 0; hc < 2; hc++) {
                const int nn = bn*128 + hc*64 + cx*4;
                ulonglong2 bv = *(const ulonglong2*)&bias[nn];
                ull e0 = acc2[r16][hc*2+0], e1 = acc2[r16][hc*2+1];
                add2(e0, bv.x); add2(e1, bv.y);
                ulonglong2 o; o.x = e0; o.y = e1;
                *(ulonglong2*)&out[m*C_ + nn] = o;
            }
        }
}

// ---------------------------------------------------------------------------
// Attention: block = (128 q-rows, bh), 256 threads, micro 4x8.
// No online max; exp2 (log2e folded into Q); row-sum shuffles deferred to end.
// smem (dynamic): Qt[64][128] | Kt[64][*68] | Vs[64][*68] | Pt[64][*132]
// ---------------------------------------------------------------------------
#define KT_S 68
#define VS_S 68
#define PT_S 132
#define ATTN_SMEM ((64*128 + 64*KT_S + 64*VS_S + 64*PT_S) * 4)

__global__ void __launch_bounds__(256) attn_kernel() {
    extern __shared__ float smf[];
    float* Qt = smf;                   // [d][i]   stride 128
    float* Kt = Qt + 64*128;           // [d][j]   stride KT_S
    float* Vs = Kt + 64*KT_S;          // [j][d]   stride VS_S
    float* Pt = Vs + 64*VS_S;          // [j][i]   stride PT_S

    const int t  = threadIdx.x;
    const int tx = t & 7;
    const int ty = t >> 3;
    const int it = blockIdx.x;
    const int bh = blockIdx.y;
    const size_t base = (size_t)bh * (N_*D_);

    {
        const int row = t & 127, dh = (t >> 7) * 32;
        const float* Qg = g_q + base + (size_t)(it*128 + row) * D_ + dh;
        #pragma unroll
        for (int q4 = 0; q4 < 8; q4++) {
            float4 v = *(const float4*)(Qg + q4*4);
            Qt[(dh + q4*4+0)*128 + row] = v.x;
            Qt[(dh + q4*4+1)*128 + row] = v.y;
            Qt[(dh + q4*4+2)*128 + row] = v.z;
            Qt[(dh + q4*4+3)*128 + row] = v.w;
        }
    }

    ull O2[4][4] = {};
    float lrun[4] = {0.f, 0.f, 0.f, 0.f};   // per-thread partial row sums

    const int j64 = t & 63;
    const int dc  = (t >> 6) * 16;

    for (int jt = 0; jt < 32; jt++) {
        __syncthreads();
        {
            const float* Kg = g_k + base + (size_t)(jt*64 + j64)*D_ + dc;
            const float* Vg = g_v + base + (size_t)(jt*64 + j64)*D_ + dc;
            #pragma unroll
            for (int q4 = 0; q4 < 4; q4++) {
                float4 kv = *(const float4*)(Kg + q4*4);
                Kt[(dc + q4*4+0)*KT_S + j64] = kv.x;
                Kt[(dc + q4*4+1)*KT_S + j64] = kv.y;
                Kt[(dc + q4*4+2)*KT_S + j64] = kv.z;
                Kt[(dc + q4*4+3)*KT_S + j64] = kv.w;
                *(float4*)&Vs[j64*VS_S + dc + q4*4] = *(const float4*)(Vg + q4*4);
            }
        }
        __syncthreads();

        // S = Q K^T (log2e*scale folded into Q)
        ull s2[4][4] = {};
        #pragma unroll 8
        for (int d = 0; d < 64; d++) {
            float4 a0 = *(const float4*)&Qt[d*128 + ty*4];
            ulonglong2 b0 = *(const ulonglong2*)&Kt[d*KT_S + tx*4];
            ulonglong2 b1 = *(const ulonglong2*)&Kt[d*KT_S + 32 + tx*4];
            float a[4] = {a0.x, a0.y, a0.z, a0.w};
            #pragma unroll
            for (int r = 0; r < 4; r++) {
                ull ap = dup2(a[r]);
                fma2(s2[r][0], ap, b0.x);
                fma2(s2[r][1], ap, b0.y);
                fma2(s2[r][2], ap, b1.x);
                fma2(s2[r][3], ap, b1.y);
            }
        }

        float s[4][8];
        #pragma unroll
        for (int r = 0; r < 4; r++)
            #pragma unroll
            for (int q = 0; q < 4; q++)
                upk2(s2[r][q], s[r][q*2], s[r][q*2+1]);

        // Mask + exp2 + per-thread partial row-sum (reduce deferred to end)
        const int dbase = it*128 - jt*64;
        #pragma unroll
        for (int r4 = 0; r4 < 4; r4++) {
            const int r = ty*4 + r4;
            float rs = 0.f;
            #pragma unroll
            for (int c8 = 0; c8 < 8; c8++) {
                const int c = ((c8 >> 2) * 32) + tx*4 + (c8 & 3);
                const int del = dbase + r - c;
                float pv = (del >= 0 && (del & 31) == 0) ? 0.f : exp2f(s[r4][c8]);
                s[r4][c8] = pv;
                rs += pv;
            }
            lrun[r4] += rs;
        }

        // Write P transposed
        #pragma unroll
        for (int c8 = 0; c8 < 8; c8++) {
            const int c = ((c8 >> 2) * 32) + tx*4 + (c8 & 3);
            *(float4*)&Pt[c*PT_S + ty*4] = make_float4(s[0][c8], s[1][c8], s[2][c8], s[3][c8]);
        }
        __syncthreads();

        // O += P V
        #pragma unroll 8
        for (int j = 0; j < 64; j++) {
            float4 p0 = *(const float4*)&Pt[j*PT_S + ty*4];
            ulonglong2 v0 = *(const ulonglong2*)&Vs[j*VS_S + tx*4];
            ulonglong2 v1 = *(const ulonglong2*)&Vs[j*VS_S + 32 + tx*4];
            float p[4] = {p0.x, p0.y, p0.z, p0.w};
            #pragma unroll
            for (int r = 0; r < 4; r++) {
                ull pp = dup2(p[r]);
                fma2(O2[r][0], pp, v0.x);
                fma2(O2[r][1], pp, v0.y);
                fma2(O2[r][2], pp, v1.x);
                fma2(O2[r][3], pp, v1.y);
            }
        }
    }

    // Final row-sum reduce (once), normalize + write [b][n][h*64+d]
    const int bb = bh >> 4, h = bh & 15;
    #pragma unroll
    for (int r4 = 0; r4 < 4; r4++) {
        float rs = lrun[r4];
        rs += __shfl_xor_sync(0xffffffffu, rs, 1);
        rs += __shfl_xor_sync(0xffffffffu, rs, 2);
        rs += __shfl_xor_sync(0xffffffffu, rs, 4);
        ull invp = dup2(1.0f / rs);
        mul2(O2[r4][0], invp); mul2(O2[r4][1], invp);
        mul2(O2[r4][2], invp); mul2(O2[r4][3], invp);
        const int gi = it*128 + ty*4 + r4;
        size_t o = ((size_t)bb*N_ + gi)*C_ + h*64;
        ulonglong2 w0; w0.x = O2[r4][0]; w0.y = O2[r4][1];
        ulonglong2 w1; w1.x = O2[r4][2]; w1.y = O2[r4][3];
        *(ulonglong2*)&g_ao[o + tx*4]      = w0;
        *(ulonglong2*)&g_ao[o + 32 + tx*4] = w1;
    }
}

extern "C" void kernel_launch(void* const* d_in, const int* in_sizes, int n_in,
                              void* d_out, int out_size) {
    const float* x    = (const float*)d_in[0];
    const float* Wqkv = (const float*)d_in[1];
    const float* Wout = (const float*)d_in[2];
    const float* bout = (const float*)d_in[3];
    float* out = (float*)d_out;

    cudaFuncSetAttribute(attn_kernel, cudaFuncAttributeMaxDynamicSharedMemorySize, ATTN_SMEM);

    gemm_qkv<<<dim3(24, 32), 128>>>(x, Wqkv);
    attn_kernel<<<dim3(16, 32), 256, ATTN_SMEM>>>();
    gemm_out<<<dim3(8, 32), 128>>>(Wout, bout, out);
}

// round 10
// speedup vs baseline: 1.2139x; 1.2139x over previous
#include <cuda_runtime.h>
#include <cuda_bf16.h>
#include <cstdint>
#include <math.h>

#define B_   2
#define H_   16
#define N_   2048
#define D_   64
#define C_   1024
#define BH_  (B_*H_)

// fp32 scratch
__device__ float g_q[BH_*N_*D_];    // [b*h][n][64], pre-scaled by log2e/32
__device__ float g_k[BH_*N_*D_];
__device__ float g_v[BH_*N_*D_];
// bf16 hi/lo scratch
__device__ __nv_bfloat16 g_xh[4096*1024], g_xl[4096*1024];     // X split, [row][k]
__device__ __nv_bfloat16 g_wqh[3072*1024], g_wql[3072*1024];   // Wqkv^T split, [n][k]
__device__ __nv_bfloat16 g_woh[1024*1024], g_wol[1024*1024];   // Wout^T split, [n][k]
__device__ __nv_bfloat16 g_aoh[4096*1024], g_aol[4096*1024];   // attn out split, [row][k]

typedef unsigned long long ull;

// ---- packed f32x2 helpers (attention) ----
__device__ __forceinline__ ull dup2(float x) {
    ull d; asm("mov.b64 %0, {%1, %1};" : "=l"(d) : "f"(x)); return d;
}
__device__ __forceinline__ void upk2(ull d, float& x, float& y) {
    asm("mov.b64 {%0, %1}, %2;" : "=f"(x), "=f"(y) : "l"(d));
}
__device__ __forceinline__ void fma2(ull& d, ull a, ull b) {
    asm("fma.rn.f32x2 %0, %1, %2, %0;" : "+l"(d) : "l"(a), "l"(b));
}
__device__ __forceinline__ void mul2(ull& d, ull a) {
    asm("mul.rn.f32x2 %0, %0, %1;" : "+l"(d) : "l"(a));
}

// ---- mma helpers ----
__device__ __forceinline__ uint32_t smem_u32(const void* p) {
    uint32_t a;
    asm("{ .reg .u64 t; cvta.to.shared.u64 t, %1; cvt.u32.u64 %0, t; }" : "=r"(a) : "l"(p));
    return a;
}
__device__ __forceinline__ void ldmx4(uint32_t* r, uint32_t addr) {
    asm volatile("ldmatrix.sync.aligned.m8n8.x4.shared.b16 {%0,%1,%2,%3}, [%4];"
                 : "=r"(r[0]), "=r"(r[1]), "=r"(r[2]), "=r"(r[3]) : "r"(addr));
}
__device__ __forceinline__ void mma_bf16(float* d, const uint32_t* a, uint32_t b0, uint32_t b1) {
    asm volatile("mma.sync.aligned.m16n8k16.row.col.f32.bf16.bf16.f32 "
                 "{%0,%1,%2,%3}, {%4,%5,%6,%7}, {%8,%9}, {%0,%1,%2,%3};"
                 : "+f"(d[0]), "+f"(d[1]), "+f"(d[2]), "+f"(d[3])
                 : "r"(a[0]), "r"(a[1]), "r"(a[2]), "r"(a[3]), "r"(b0), "r"(b1));
}
__device__ __forceinline__ void bsplit(float v, __nv_bfloat16& h, __nv_bfloat16& l) {
    h = __float2bfloat16_rn(v);
    l = __float2bfloat16_rn(v - __bfloat162float(h));
}

// ===========================================================================
// Splitters
// ===========================================================================
__global__ void __launch_bounds__(256) split_x(const float* __restrict__ X) {
    int i = blockIdx.x*256 + threadIdx.x;            // 4096 blocks * 256 = 1M float4
    float4 v = ((const float4*)X)[i];
    __nv_bfloat16 h[4], l[4];
    bsplit(v.x, h[0], l[0]); bsplit(v.y, h[1], l[1]);
    bsplit(v.z, h[2], l[2]); bsplit(v.w, h[3], l[3]);
    *(uint2*)&g_xh[(size_t)i*4] = *(uint2*)h;
    *(uint2*)&g_xl[(size_t)i*4] = *(uint2*)l;
}

// Transpose + split: W[K][Nn] -> T[Nn][K] (hi/lo). which: 0=Wqkv, 1=Wout.
__global__ void __launch_bounds__(256) split_wT(const float* __restrict__ W, int Nn, int which) {
    __shared__ float sm[32][33];
    const int tx = threadIdx.x, ty = threadIdx.y;    // 32 x 8
    const int nx = blockIdx.x*32, kx = blockIdx.y*32;
    #pragma unroll
    for (int i = 0; i < 4; i++)
        sm[ty + i*8][tx] = W[(size_t)(kx + ty + i*8)*Nn + nx + tx];
    __syncthreads();
    __nv_bfloat16* Th = which ? g_woh : g_wqh;
    __nv_bfloat16* Tl = which ? g_wol : g_wql;
    #pragma unroll
    for (int i = 0; i < 4; i++) {
        float v = sm[tx][ty + i*8];
        __nv_bfloat16 h, l; bsplit(v, h, l);
        size_t o = (size_t)(nx + ty + i*8)*1024 + kx + tx;
        Th[o] = h; Tl[o] = l;
    }
}

// ===========================================================================
// bf16 3-pass mma GEMM. CTA 128(m)x128(n), 256 thr (8 warps, 2m x 4n),
// warp tile 64x32 (4 m-tiles x 4 n-tiles of m16n8k16). K chunks of 16,
// double-buffered smem; layout [kc][row][8 bf16] (16B cells, ldmatrix-clean).
// Stage: Ah@0 Al@4096 Bh@8192 Bl@12288 (bytes), 16KB/stage.
// ===========================================================================
struct MmaCore {
    float acc[4][4][4];
    uint32_t sb;            // smem base
    int offA, offB;         // ldmatrix lane offsets (bytes, within region)
    int wm, wn, lane;
    const uint4 *pAh, *pAl, *pBh, *pBl;
    uint4 rAh, rAl, rBh, rBl;
    int sA, sBo;            // store offsets (bytes)
};

__device__ __forceinline__ void mma_init(MmaCore& c, void* smem,
        const __nv_bfloat16* Ah, const __nv_bfloat16* Al,
        const __nv_bfloat16* Bh, const __nv_bfloat16* Bl,
        int bm, int bn) {
    const int t = threadIdx.x, l = t & 31, w = t >> 5;
    c.lane = l; c.wm = w & 1; c.wn = w >> 1;
    c.sb = smem_u32(smem);
    #pragma unroll
    for (int a = 0; a < 4; a++)
        #pragma unroll
        for (int b = 0; b < 4; b++)
            #pragma unroll
            for (int d = 0; d < 4; d++) c.acc[a][b][d] = 0.f;

    const int arow = t & 127, akc = t >> 7;
    c.pAh = (const uint4*)(Ah + (size_t)(bm*128 + arow)*1024) + akc;
    c.pAl = (const uint4*)(Al + (size_t)(bm*128 + arow)*1024) + akc;
    c.pBh = (const uint4*)(Bh + (size_t)(bn*128 + arow)*1024) + akc;
    c.pBl = (const uint4*)(Bl + (size_t)(bn*128 + arow)*1024) + akc;
    c.sA = (akc*128 + arow)*16;
    c.sBo = c.sA;
    // ldmatrix lane offsets
    const int rowA = c.wm*64 + ((l>>3)&1)*8 + (l&7), kcA = l>>4;
    c.offA = (kcA*128 + rowA)*16;
    const int nB = c.wn*32 + (l&7) + (l>>4)*8, kcB = (l>>3)&1;
    c.offB = (kcB*128 + nB)*16;
}

__device__ __forceinline__ void mma_fetch(MmaCore& c) {
    c.rAh = *c.pAh; c.rAl = *c.pAl; c.rBh = *c.pBh; c.rBl = *c.pBl;
    c.pAh += 2; c.pAl += 2; c.pBh += 2; c.pBl += 2;
}
__device__ __forceinline__ void mma_store(MmaCore& c, int s, char* smem) {
    char* S = smem + s*16384;
    *(uint4*)(S + c.sA)          = c.rAh;
    *(uint4*)(S + 4096 + c.sA)   = c.rAl;
    *(uint4*)(S + 8192 + c.sBo)  = c.rBh;
    *(uint4*)(S + 12288 + c.sBo) = c.rBl;
}
__device__ __forceinline__ void mma_compute(MmaCore& c, int s) {
    const uint32_t S = c.sb + s*16384;
    uint32_t Ah_[4][4], Al_[4][4];
    #pragma unroll
    for (int mt = 0; mt < 4; mt++) {
        ldmx4(Ah_[mt], S + c.offA + mt*256);
        ldmx4(Al_[mt], S + 4096 + c.offA + mt*256);
    }
    #pragma unroll
    for (int ntp = 0; ntp < 2; ntp++) {
        uint32_t bh[4], bl[4];
        ldmx4(bh, S + 8192 + c.offB + ntp*256);
        ldmx4(bl, S + 12288 + c.offB + ntp*256);
        #pragma unroll
        for (int n2 = 0; n2 < 2; n2++) {
            const int nt = ntp*2 + n2;
            const uint32_t b0h = bh[n2*2], b1h = bh[n2*2+1];
            const uint32_t b0l = bl[n2*2], b1l = bl[n2*2+1];
            #pragma unroll
            for (int mt = 0; mt < 4; mt++) {
                mma_bf16(c.acc[mt][nt], Ah_[mt], b0h, b1h);
                mma_bf16(c.acc[mt][nt], Ah_[mt], b0l, b1l);
                mma_bf16(c.acc[mt][nt], Al_[mt], b0h, b1h);
            }
        }
    }
}

#define MMA_MAIN(core, smem_char)                          \
    mma_fetch(core); mma_store(core, 0, smem_char);        \
    __syncthreads();                                       \
    for (int j = 0; j < 64; j++) {                         \
        if (j < 63) mma_fetch(core);                       \
        mma_compute(core, j & 1);                          \
        if (j < 63) { mma_store(core, (j+1)&1, smem_char); __syncthreads(); } \
    }

__global__ void __launch_bounds__(256) gemm_qkv_mma() {
    __shared__ __align__(16) char smem[2*16384];
    MmaCore c;
    const int bn = blockIdx.x, bm = blockIdx.y;    // bn 0..23, bm 0..31
    mma_init(c, smem, g_xh, g_xl, g_wqh, g_wql, bm, bn);
    MMA_MAIN(c, smem);

    const int sel = bn >> 3;
    float* dst = (sel == 0) ? g_q : (sel == 1) ? g_k : g_v;
    const float sc = (sel == 0) ? 0.03125f * 1.4426950408889634f : 1.0f;
    #pragma unroll
    for (int mt = 0; mt < 4; mt++) {
        const int row0 = bm*128 + c.wm*64 + mt*16 + (c.lane >> 2);
        #pragma unroll
        for (int nt = 0; nt < 4; nt++) {
            const int col = ((bn & 7)*128 + c.wn*32 + nt*8 + (c.lane & 3)*2);
            const int h = col >> 6, d = col & 63;
            #pragma unroll
            for (int half = 0; half < 2; half++) {
                const int r = row0 + half*8;
                const int bb = r >> 11, nr = r & 2047;
                float2 o = make_float2(c.acc[mt][nt][half*2+0]*sc, c.acc[mt][nt][half*2+1]*sc);
                *(float2*)&dst[(((size_t)(bb*H_ + h))*N_ + nr)*D_ + d] = o;
            }
        }
    }
}

__global__ void __launch_bounds__(256) gemm_out_mma(const float* __restrict__ bias,
                                                    float* __restrict__ out) {
    __shared__ __align__(16) char smem[2*16384];
    MmaCore c;
    const int bn = blockIdx.x, bm = blockIdx.y;    // bn 0..7, bm 0..31
    mma_init(c, smem, g_aoh, g_aol, g_woh, g_wol, bm, bn);
    MMA_MAIN(c, smem);

    #pragma unroll
    for (int mt = 0; mt < 4; mt++) {
        const int row0 = bm*128 + c.wm*64 + mt*16 + (c.lane >> 2);
        #pragma unroll
        for (int nt = 0; nt < 4; nt++) {
            const int col = bn*128 + c.wn*32 + nt*8 + (c.lane & 3)*2;
            const float2 bv = *(const float2*)&bias[col];
            #pragma unroll
            for (int half = 0; half < 2; half++) {
                const size_t r = (size_t)(row0 + half*8);
                float2 o = make_float2(c.acc[mt][nt][half*2+0] + bv.x,
                                       c.acc[mt][nt][half*2+1] + bv.y);
                *(float2*)&out[r*C_ + col] = o;
            }
        }
    }
}

// ---------------------------------------------------------------------------
// Attention (R9): 128x64 tiles, 256 threads, micro 4x8, exp2, deferred reduce.
// Epilogue writes bf16 hi/lo of AO for the mma output GEMM.
// ---------------------------------------------------------------------------
#define KT_S 68
#define VS_S 68
#define PT_S 132
#define ATTN_SMEM ((64*128 + 64*KT_S + 64*VS_S + 64*PT_S) * 4)

__global__ void __launch_bounds__(256) attn_kernel() {
    extern __shared__ float smf[];
    float* Qt = smf;
    float* Kt = Qt + 64*128;
    float* Vs = Kt + 64*KT_S;
    float* Pt = Vs + 64*VS_S;

    const int t  = threadIdx.x;
    const int tx = t & 7;
    const int ty = t >> 3;
    const int it = blockIdx.x;
    const int bh = blockIdx.y;
    const size_t base = (size_t)bh * (N_*D_);

    {
        const int row = t & 127, dh = (t >> 7) * 32;
        const float* Qg = g_q + base + (size_t)(it*128 + row) * D_ + dh;
        #pragma unroll
        for (int q4 = 0; q4 < 8; q4++) {
            float4 v = *(const float4*)(Qg + q4*4);
            Qt[(dh + q4*4+0)*128 + row] = v.x;
            Qt[(dh + q4*4+1)*128 + row] = v.y;
            Qt[(dh + q4*4+2)*128 + row] = v.z;
            Qt[(dh + q4*4+3)*128 + row] = v.w;
        }
    }

    ull O2[4][4] = {};
    float lrun[4] = {0.f, 0.f, 0.f, 0.f};

    const int j64 = t & 63;
    const int dc  = (t >> 6) * 16;

    for (int jt = 0; jt < 32; jt++) {
        __syncthreads();
        {
            const float* Kg = g_k + base + (size_t)(jt*64 + j64)*D_ + dc;
            const float* Vg = g_v + base + (size_t)(jt*64 + j64)*D_ + dc;
            #pragma unroll
            for (int q4 = 0; q4 < 4; q4++) {
                float4 kv = *(const float4*)(Kg + q4*4);
                Kt[(dc + q4*4+0)*KT_S + j64] = kv.x;
                Kt[(dc + q4*4+1)*KT_S + j64] = kv.y;
                Kt[(dc + q4*4+2)*KT_S + j64] = kv.z;
                Kt[(dc + q4*4+3)*KT_S + j64] = kv.w;
                *(float4*)&Vs[j64*VS_S + dc + q4*4] = *(const float4*)(Vg + q4*4);
            }
        }
        __syncthreads();

        ull s2[4][4] = {};
        #pragma unroll 8
        for (int d = 0; d < 64; d++) {
            float4 a0 = *(const float4*)&Qt[d*128 + ty*4];
            ulonglong2 b0 = *(const ulonglong2*)&Kt[d*KT_S + tx*4];
            ulonglong2 b1 = *(const ulonglong2*)&Kt[d*KT_S + 32 + tx*4];
            float a[4] = {a0.x, a0.y, a0.z, a0.w};
            #pragma unroll
            for (int r = 0; r < 4; r++) {
                ull ap = dup2(a[r]);
                fma2(s2[r][0], ap, b0.x);
                fma2(s2[r][1], ap, b0.y);
                fma2(s2[r][2], ap, b1.x);
                fma2(s2[r][3], ap, b1.y);
            }
        }

        float s[4][8];
        #pragma unroll
        for (int r = 0; r < 4; r++)
            #pragma unroll
            for (int q = 0; q < 4; q++)
                upk2(s2[r][q], s[r][q*2], s[r][q*2+1]);

        const int dbase = it*128 - jt*64;
        #pragma unroll
        for (int r4 = 0; r4 < 4; r4++) {
            const int r = ty*4 + r4;
            float rs = 0.f;
            #pragma unroll
            for (int c8 = 0; c8 < 8; c8++) {
                const int cc = ((c8 >> 2) * 32) + tx*4 + (c8 & 3);
                const int del = dbase + r - cc;
                float pv = (del >= 0 && (del & 31) == 0) ? 0.f : exp2f(s[r4][c8]);
                s[r4][c8] = pv;
                rs += pv;
            }
            lrun[r4] += rs;
        }

        #pragma unroll
        for (int c8 = 0; c8 < 8; c8++) {
            const int cc = ((c8 >> 2) * 32) + tx*4 + (c8 & 3);
            *(float4*)&Pt[cc*PT_S + ty*4] = make_float4(s[0][c8], s[1][c8], s[2][c8], s[3][c8]);
        }
        __syncthreads();

        #pragma unroll 8
        for (int j = 0; j < 64; j++) {
            float4 p0 = *(const float4*)&Pt[j*PT_S + ty*4];
            ulonglong2 v0 = *(const ulonglong2*)&Vs[j*VS_S + tx*4];
            ulonglong2 v1 = *(const ulonglong2*)&Vs[j*VS_S + 32 + tx*4];
            float p[4] = {p0.x, p0.y, p0.z, p0.w};
            #pragma unroll
            for (int r = 0; r < 4; r++) {
                ull pp = dup2(p[r]);
                fma2(O2[r][0], pp, v0.x);
                fma2(O2[r][1], pp, v0.y);
                fma2(O2[r][2], pp, v1.x);
                fma2(O2[r][3], pp, v1.y);
            }
        }
    }

    // Final reduce + normalize + bf16 hi/lo write to [row=b*2048+gi][col=h*64+d]
    const int bb = bh >> 4, h = bh & 15;
    #pragma unroll
    for (int r4 = 0; r4 < 4; r4++) {
        float rs = lrun[r4];
        rs += __shfl_xor_sync(0xffffffffu, rs, 1);
        rs += __shfl_xor_sync(0xffffffffu, rs, 2);
        rs += __shfl_xor_sync(0xffffffffu, rs, 4);
        ull invp = dup2(1.0f / rs);
        mul2(O2[r4][0], invp); mul2(O2[r4][1], invp);
        mul2(O2[r4][2], invp); mul2(O2[r4][3], invp);
        float o[8];
        upk2(O2[r4][0], o[0], o[1]); upk2(O2[r4][1], o[2], o[3]);
        upk2(O2[r4][2], o[4], o[5]); upk2(O2[r4][3], o[6], o[7]);
        const int gi = it*128 + ty*4 + r4;
        const size_t rowbase = ((size_t)bb*N_ + gi)*C_ + h*64;
        __nv_bfloat16 hh[8], ll[8];
        #pragma unroll
        for (int q = 0; q < 8; q++) bsplit(o[q], hh[q], ll[q]);
        *(uint2*)&g_aoh[rowbase + tx*4]      = *(uint2*)&hh[0];
        *(uint2*)&g_aoh[rowbase + 32 + tx*4] = *(uint2*)&hh[4];
        *(uint2*)&g_aol[rowbase + tx*4]      = *(uint2*)&ll[0];
        *(uint2*)&g_aol[rowbase + 32 + tx*4] = *(uint2*)&ll[4];
    }
}

extern "C" void kernel_launch(void* const* d_in, const int* in_sizes, int n_in,
                              void* d_out, int out_size) {
    const float* x    = (const float*)d_in[0];
    const float* Wqkv = (const float*)d_in[1];
    const float* Wout = (const float*)d_in[2];
    const float* bout = (const float*)d_in[3];
    float* out = (float*)d_out;

    cudaFuncSetAttribute(attn_kernel, cudaFuncAttributeMaxDynamicSharedMemorySize, ATTN_SMEM);

    split_x<<<4096, 256>>>(x);
    split_wT<<<dim3(96, 32), dim3(32, 8)>>>(Wqkv, 3072, 0);
    split_wT<<<dim3(32, 32), dim3(32, 8)>>>(Wout, 1024, 1);
    gemm_qkv_mma<<<dim3(24, 32), 256>>>();
    attn_kernel<<<dim3(16, 32), 256, ATTN_SMEM>>>();
    gemm_out_mma<<<dim3(8, 32), 256>>>(bout, out);
}

// round 11
// speedup vs baseline: 1.9398x; 1.5979x over previous
#include <cuda_runtime.h>
#include <cuda_bf16.h>
#include <cstdint>
#include <math.h>

#define B_   2
#define H_   16
#define N_   2048
#define D_   64
#define C_   1024
#define BH_  (B_*H_)

// bf16 hi/lo scratch
__device__ __nv_bfloat16 g_xh[4096*1024], g_xl[4096*1024];     // X split, [row][k]
__device__ __nv_bfloat16 g_wqh[3072*1024], g_wql[3072*1024];   // Wqkv^T split, [n][k]
__device__ __nv_bfloat16 g_woh[1024*1024], g_wol[1024*1024];   // Wout^T split, [n][k]
__device__ __nv_bfloat16 g_aoh[4096*1024], g_aol[4096*1024];   // attn out split, [row][k]
// attention operands (written by gemm_qkv_mma epilogue)
__device__ __nv_bfloat16 g_qh2[BH_*N_*D_], g_ql2[BH_*N_*D_];   // [bh][tok][64], *log2e/32
__device__ __nv_bfloat16 g_kh2[BH_*N_*D_], g_kl2[BH_*N_*D_];   // [bh][tok][64]
__device__ __nv_bfloat16 g_vth[BH_*N_*D_], g_vtl[BH_*N_*D_];   // [bh][d][tok]  (transposed)

// ---- mma helpers ----
__device__ __forceinline__ uint32_t smem_u32(const void* p) {
    uint32_t a;
    asm("{ .reg .u64 t; cvta.to.shared.u64 t, %1; cvt.u32.u64 %0, t; }" : "=r"(a) : "l"(p));
    return a;
}
__device__ __forceinline__ void ldmx4(uint32_t* r, uint32_t addr) {
    asm volatile("ldmatrix.sync.aligned.m8n8.x4.shared.b16 {%0,%1,%2,%3}, [%4];"
                 : "=r"(r[0]), "=r"(r[1]), "=r"(r[2]), "=r"(r[3]) : "r"(addr));
}
__device__ __forceinline__ void mma_bf16(float* d, const uint32_t* a, uint32_t b0, uint32_t b1) {
    asm volatile("mma.sync.aligned.m16n8k16.row.col.f32.bf16.bf16.f32 "
                 "{%0,%1,%2,%3}, {%4,%5,%6,%7}, {%8,%9}, {%0,%1,%2,%3};"
                 : "+f"(d[0]), "+f"(d[1]), "+f"(d[2]), "+f"(d[3])
                 : "r"(a[0]), "r"(a[1]), "r"(a[2]), "r"(a[3]), "r"(b0), "r"(b1));
}
__device__ __forceinline__ void bsplit(float v, __nv_bfloat16& h, __nv_bfloat16& l) {
    h = __float2bfloat16_rn(v);
    l = __float2bfloat16_rn(v - __bfloat162float(h));
}
__device__ __forceinline__ uint32_t pack_bf2(__nv_bfloat16 lo, __nv_bfloat16 hi) {
    __nv_bfloat162 p; p.x = lo; p.y = hi;
    return *(uint32_t*)&p;
}

// ===========================================================================
// Splitters
// ===========================================================================
__global__ void __launch_bounds__(256) split_x(const float* __restrict__ X) {
    int i = blockIdx.x*256 + threadIdx.x;
    float4 v = ((const float4*)X)[i];
    __nv_bfloat16 h[4], l[4];
    bsplit(v.x, h[0], l[0]); bsplit(v.y, h[1], l[1]);
    bsplit(v.z, h[2], l[2]); bsplit(v.w, h[3], l[3]);
    *(uint2*)&g_xh[(size_t)i*4] = *(uint2*)h;
    *(uint2*)&g_xl[(size_t)i*4] = *(uint2*)l;
}

__global__ void __launch_bounds__(256) split_wT(const float* __restrict__ W, int Nn, int which) {
    __shared__ float sm[32][33];
    const int tx = threadIdx.x, ty = threadIdx.y;
    const int nx = blockIdx.x*32, kx = blockIdx.y*32;
    #pragma unroll
    for (int i = 0; i < 4; i++)
        sm[ty + i*8][tx] = W[(size_t)(kx + ty + i*8)*Nn + nx + tx];
    __syncthreads();
    __nv_bfloat16* Th = which ? g_woh : g_wqh;
    __nv_bfloat16* Tl = which ? g_wol : g_wql;
    #pragma unroll
    for (int i = 0; i < 4; i++) {
        float v = sm[tx][ty + i*8];
        __nv_bfloat16 h, l; bsplit(v, h, l);
        size_t o = (size_t)(nx + ty + i*8)*1024 + kx + tx;
        Th[o] = h; Tl[o] = l;
    }
}

// ===========================================================================
// bf16 3-pass mma GEMM (as R10). CTA 128x128, 8 warps, warp 64x32.
// ===========================================================================
struct MmaCore {
    float acc[4][4][4];
    uint32_t sb;
    int offA, offB;
    int wm, wn, lane;
    const uint4 *pAh, *pAl, *pBh, *pBl;
    uint4 rAh, rAl, rBh, rBl;
    int sA, sBo;
};

__device__ __forceinline__ void mma_init(MmaCore& c, void* smem,
        const __nv_bfloat16* Ah, const __nv_bfloat16* Al,
        const __nv_bfloat16* Bh, const __nv_bfloat16* Bl,
        int bm, int bn) {
    const int t = threadIdx.x, l = t & 31, w = t >> 5;
    c.lane = l; c.wm = w & 1; c.wn = w >> 1;
    c.sb = smem_u32(smem);
    #pragma unroll
    for (int a = 0; a < 4; a++)
        #pragma unroll
        for (int b = 0; b < 4; b++)
            #pragma unroll
            for (int d = 0; d < 4; d++) c.acc[a][b][d] = 0.f;

    const int arow = t & 127, akc = t >> 7;
    c.pAh = (const uint4*)(Ah + (size_t)(bm*128 + arow)*1024) + akc;
    c.pAl = (const uint4*)(Al + (size_t)(bm*128 + arow)*1024) + akc;
    c.pBh = (const uint4*)(Bh + (size_t)(bn*128 + arow)*1024) + akc;
    c.pBl = (const uint4*)(Bl + (size_t)(bn*128 + arow)*1024) + akc;
    c.sA = (akc*128 + arow)*16;
    c.sBo = c.sA;
    const int rowA = c.wm*64 + ((l>>3)&1)*8 + (l&7), kcA = l>>4;
    c.offA = (kcA*128 + rowA)*16;
    const int nB = c.wn*32 + (l&7) + (l>>4)*8, kcB = (l>>3)&1;
    c.offB = (kcB*128 + nB)*16;
}

__device__ __forceinline__ void mma_fetch(MmaCore& c) {
    c.rAh = *c.pAh; c.rAl = *c.pAl; c.rBh = *c.pBh; c.rBl = *c.pBl;
    c.pAh += 2; c.pAl += 2; c.pBh += 2; c.pBl += 2;
}
__device__ __forceinline__ void mma_store(MmaCore& c, int s, char* smem) {
    char* S = smem + s*16384;
    *(uint4*)(S + c.sA)          = c.rAh;
    *(uint4*)(S + 4096 + c.sA)   = c.rAl;
    *(uint4*)(S + 8192 + c.sBo)  = c.rBh;
    *(uint4*)(S + 12288 + c.sBo) = c.rBl;
}
__device__ __forceinline__ void mma_compute(MmaCore& c, int s) {
    const uint32_t S = c.sb + s*16384;
    uint32_t Ah_[4][4], Al_[4][4];
    #pragma unroll
    for (int mt = 0; mt < 4; mt++) {
        ldmx4(Ah_[mt], S + c.offA + mt*256);
        ldmx4(Al_[mt], S + 4096 + c.offA + mt*256);
    }
    #pragma unroll
    for (int ntp = 0; ntp < 2; ntp++) {
        uint32_t bh[4], bl[4];
        ldmx4(bh, S + 8192 + c.offB + ntp*256);
        ldmx4(bl, S + 12288 + c.offB + ntp*256);
        #pragma unroll
        for (int n2 = 0; n2 < 2; n2++) {
            const int nt = ntp*2 + n2;
            #pragma unroll
            for (int mt = 0; mt < 4; mt++) {
                mma_bf16(c.acc[mt][nt], Ah_[mt], bh[n2*2], bh[n2*2+1]);
                mma_bf16(c.acc[mt][nt], Ah_[mt], bl[n2*2], bl[n2*2+1]);
                mma_bf16(c.acc[mt][nt], Al_[mt], bh[n2*2], bh[n2*2+1]);
            }
        }
    }
}

#define MMA_MAIN(core, smem_char)                          \
    mma_fetch(core); mma_store(core, 0, smem_char);        \
    __syncthreads();                                       \
    for (int j = 0; j < 64; j++) {                         \
        if (j < 63) mma_fetch(core);                       \
        mma_compute(core, j & 1);                          \
        if (j < 63) { mma_store(core, (j+1)&1, smem_char); __syncthreads(); } \
    }

__global__ void __launch_bounds__(256) gemm_qkv_mma() {
    __shared__ __align__(16) char smem[2*16384];
    MmaCore c;
    const int bn = blockIdx.x, bm = blockIdx.y;
    mma_init(c, smem, g_xh, g_xl, g_wqh, g_wql, bm, bn);
    MMA_MAIN(c, smem);

    const int sel = bn >> 3;
    const float sc = (sel == 0) ? 0.03125f * 1.4426950408889634f : 1.0f;
    #pragma unroll
    for (int mt = 0; mt < 4; mt++) {
        const int row0 = bm*128 + c.wm*64 + mt*16 + (c.lane >> 2);
        #pragma unroll
        for (int nt = 0; nt < 4; nt++) {
            const int col = (bn & 7)*128 + c.wn*32 + nt*8 + (c.lane & 3)*2;
            const int h = col >> 6, d = col & 63;
            #pragma unroll
            for (int half = 0; half < 2; half++) {
                const int r = row0 + half*8;
                const int bb = r >> 11, nr = r & 2047;
                const int bh_ = bb*H_ + h;
                float f0 = c.acc[mt][nt][half*2+0]*sc;
                float f1 = c.acc[mt][nt][half*2+1]*sc;
                __nv_bfloat16 h0,l0,h1,l1;
                bsplit(f0, h0, l0); bsplit(f1, h1, l1);
                if (sel == 2) {
                    // V transposed: [bh][d][tok]
                    size_t o = ((size_t)bh_*D_ + d)*N_ + nr;
                    g_vth[o] = h0; g_vtl[o] = l0;
                    g_vth[o + N_] = h1; g_vtl[o + N_] = l1;
                } else {
                    size_t o = ((size_t)bh_*N_ + nr)*D_ + d;
                    __nv_bfloat16* Dh = sel ? g_kh2 : g_qh2;
                    __nv_bfloat16* Dl = sel ? g_kl2 : g_ql2;
                    *(uint32_t*)&Dh[o] = pack_bf2(h0, h1);
                    *(uint32_t*)&Dl[o] = pack_bf2(l0, l1);
                }
            }
        }
    }
}

__global__ void __launch_bounds__(256) gemm_out_mma(const float* __restrict__ bias,
                                                    float* __restrict__ out) {
    __shared__ __align__(16) char smem[2*16384];
    MmaCore c;
    const int bn = blockIdx.x, bm = blockIdx.y;
    mma_init(c, smem, g_aoh, g_aol, g_woh, g_wol, bm, bn);
    MMA_MAIN(c, smem);

    #pragma unroll
    for (int mt = 0; mt < 4; mt++) {
        const int row0 = bm*128 + c.wm*64 + mt*16 + (c.lane >> 2);
        #pragma unroll
        for (int nt = 0; nt < 4; nt++) {
            const int col = bn*128 + c.wn*32 + nt*8 + (c.lane & 3)*2;
            const float2 bv = *(const float2*)&bias[col];
            #pragma unroll
            for (int half = 0; half < 2; half++) {
                const size_t r = (size_t)(row0 + half*8);
                float2 o = make_float2(c.acc[mt][nt][half*2+0] + bv.x,
                                       c.acc[mt][nt][half*2+1] + bv.y);
                *(float2*)&out[r*C_ + col] = o;
            }
        }
    }
}

// ===========================================================================
// Attention on mma.sync: CTA = (it: 128 q-rows, bh). 8 warps x 16 rows each,
// each warp covers all 64 keys of the j-tile. 3-pass everywhere.
// smem: sQh[8kcb][128][16B] 16K | sQl 16K | sKh[8kcb_d][64j][16B] 8K | sKl 8K
//       | sVh[8kcb_j][64d][16B] 8K | sVl 8K   = 64KB dynamic
// ===========================================================================
#define ATTN_SMEM 65536

__global__ void __launch_bounds__(256) attn_mma() {
    extern __shared__ __align__(16) char smem[];
    char* sQ = smem;                 // h @0, l @16384
    char* sK = smem + 32768;         // h @0, l @8192
    char* sV = smem + 49152;         // h @0, l @8192
    const uint32_t sbQ = smem_u32(sQ), sbK = smem_u32(sK), sbV = smem_u32(sV);

    const int t = threadIdx.x, l = t & 31, w = t >> 5;
    const int it = blockIdx.x, bh = blockIdx.y;
    const size_t base = (size_t)bh * (N_*D_);

    // ---- load Q tile into smem: [kcb][row][16B] ----
    {
        const int row = t & 127;
        const int kcb0 = (t >> 7) * 4;
        const uint4* gh = (const uint4*)(g_qh2 + base + (size_t)(it*128 + row)*D_);
        const uint4* gl = (const uint4*)(g_ql2 + base + (size_t)(it*128 + row)*D_);
        #pragma unroll
        for (int u = 0; u < 4; u++) {
            const int kcb = kcb0 + u;
            *(uint4*)(sQ + (kcb*128 + row)*16)         = gh[kcb];
            *(uint4*)(sQ + 16384 + (kcb*128 + row)*16) = gl[kcb];
        }
    }

    // ldmatrix lane offsets
    const int rowQ = w*16 + ((l>>3)&1)*8 + (l&7);
    const int offQ = rowQ*16 + (l>>4)*2048;                    // + kc*4096
    const int offB = (((l>>3)&1)*64 + (l&7) + (l>>4)*8)*16;    // + kc*2048 + np*256

    // K/V tile loader offsets
    const int jrow = t & 63;
    const int kcb2 = (t >> 6) * 2;

    float oacc[8][4];
    #pragma unroll
    for (int nt = 0; nt < 8; nt++)
        #pragma unroll
        for (int d = 0; d < 4; d++) oacc[nt][d] = 0.f;
    float lrun0 = 0.f, lrun1 = 0.f;

    const int row_glob0 = it*128 + w*16 + (l>>2);

    for (int jt = 0; jt < 32; jt++) {
        __syncthreads();   // prev compute done with sK/sV; (first iter: Q stores visible)
        {
            const uint4* kh = (const uint4*)(g_kh2 + base + (size_t)(jt*64 + jrow)*D_);
            const uint4* kl = (const uint4*)(g_kl2 + base + (size_t)(jt*64 + jrow)*D_);
            const uint4* vh = (const uint4*)(g_vth + base + (size_t)jrow*N_ + jt*64);
            const uint4* vl = (const uint4*)(g_vtl + base + (size_t)jrow*N_ + jt*64);
            #pragma unroll
            for (int u = 0; u < 2; u++) {
                const int kcb = kcb2 + u;
                *(uint4*)(sK + (kcb*64 + jrow)*16)        = kh[kcb];
                *(uint4*)(sK + 8192 + (kcb*64 + jrow)*16) = kl[kcb];
                *(uint4*)(sV + (kcb*64 + jrow)*16)        = vh[kcb];
                *(uint4*)(sV + 8192 + (kcb*64 + jrow)*16) = vl[kcb];
            }
        }
        __syncthreads();

        // ---- S = Q K^T (3-pass), c-frags sacc[8 n8][4] ----
        float sacc[8][4];
        #pragma unroll
        for (int nt = 0; nt < 8; nt++)
            #pragma unroll
            for (int d = 0; d < 4; d++) sacc[nt][d] = 0.f;

        #pragma unroll
        for (int kc = 0; kc < 4; kc++) {
            uint32_t qh[4], ql[4];
            ldmx4(qh, sbQ + offQ + kc*4096);
            ldmx4(ql, sbQ + 16384 + offQ + kc*4096);
            #pragma unroll
            for (int np = 0; np < 4; np++) {
                uint32_t kbh[4], kbl[4];
                ldmx4(kbh, sbK + kc*2048 + offB + np*256);
                ldmx4(kbl, sbK + 8192 + kc*2048 + offB + np*256);
                #pragma unroll
                for (int n2 = 0; n2 < 2; n2++) {
                    const int nt = np*2 + n2;
                    mma_bf16(sacc[nt], qh, kbh[n2*2], kbh[n2*2+1]);
                    mma_bf16(sacc[nt], qh, kbl[n2*2], kbl[n2*2+1]);
                    mma_bf16(sacc[nt], ql, kbh[n2*2], kbh[n2*2+1]);
                }
            }
        }

        // ---- mask + exp2 + partial row sums + pack P into a-frags ----
        uint32_t pah[4][4], pal[4][4];
        #pragma unroll
        for (int nt = 0; nt < 8; nt++) {
            const int colb = jt*64 + nt*8 + (l & 3)*2;
            const int del0 = row_glob0 - colb;          // (row, col)
            // elements: d0:(r,c) d1:(r,c+1) d2:(r+8,c) d3:(r+8,c+1)
            const int dels[4] = {del0, del0 - 1, del0 + 8, del0 + 7};
            float p[4];
            #pragma unroll
            for (int e = 0; e < 4; e++) {
                const int de = dels[e];
                const bool msk = (de >= 0) && ((de & 31) == 0);
                p[e] = msk ? 0.f : exp2f(sacc[nt][e]);
            }
            lrun0 += p[0] + p[1];
            lrun1 += p[2] + p[3];
            __nv_bfloat16 h0,l0,h1,l1,h2,l2,h3,l3;
            bsplit(p[0], h0, l0); bsplit(p[1], h1, l1);
            bsplit(p[2], h2, l2); bsplit(p[3], h3, l3);
            const int kk = nt >> 1, sl = (nt & 1)*2;
            pah[kk][sl+0] = pack_bf2(h0, h1);   // (row, k pair)
            pah[kk][sl+1] = pack_bf2(h2, h3);   // (row+8, k pair)
            pal[kk][sl+0] = pack_bf2(l0, l1);
            pal[kk][sl+1] = pack_bf2(l2, l3);
        }

        // ---- O += P V (3-pass) ----
        #pragma unroll
        for (int kk = 0; kk < 4; kk++) {
            #pragma unroll
            for (int np = 0; np < 4; np++) {
                uint32_t vbh[4], vbl[4];
                ldmx4(vbh, sbV + kk*2048 + offB + np*256);
                ldmx4(vbl, sbV + 8192 + kk*2048 + offB + np*256);
                #pragma unroll
                for (int n2 = 0; n2 < 2; n2++) {
                    const int nt = np*2 + n2;
                    mma_bf16(oacc[nt], pah[kk], vbh[n2*2], vbh[n2*2+1]);
                    mma_bf16(oacc[nt], pah[kk], vbl[n2*2], vbl[n2*2+1]);
                    mma_bf16(oacc[nt], pal[kk], vbh[n2*2], vbh[n2*2+1]);
                }
            }
        }
    }

    // ---- final: reduce row sums in-warp, normalize, split, store ----
    lrun0 += __shfl_xor_sync(0xffffffffu, lrun0, 1);
    lrun0 += __shfl_xor_sync(0xffffffffu, lrun0, 2);
    lrun1 += __shfl_xor_sync(0xffffffffu, lrun1, 1);
    lrun1 += __shfl_xor_sync(0xffffffffu, lrun1, 2);
    const float inv0 = 1.0f / lrun0, inv1 = 1.0f / lrun1;

    const int bb = bh >> 4, hh_ = bh & 15;
    #pragma unroll
    for (int nt = 0; nt < 8; nt++) {
        const int col = hh_*64 + nt*8 + (l & 3)*2;
        #pragma unroll
        for (int half = 0; half < 2; half++) {
            const float inv = half ? inv1 : inv0;
            float f0 = oacc[nt][half*2+0] * inv;
            float f1 = oacc[nt][half*2+1] * inv;
            __nv_bfloat16 h0,l0,h1,l1;
            bsplit(f0, h0, l0); bsplit(f1, h1, l1);
            const int gi = it*128 + w*16 + (l>>2) + half*8;
            const size_t o = ((size_t)bb*N_ + gi)*C_ + col;
            *(uint32_t*)&g_aoh[o] = pack_bf2(h0, h1);
            *(uint32_t*)&g_aol[o] = pack_bf2(l0, l1);
        }
    }
}

extern "C" void kernel_launch(void* const* d_in, const int* in_sizes, int n_in,
                              void* d_out, int out_size) {
    const float* x    = (const float*)d_in[0];
    const float* Wqkv = (const float*)d_in[1];
    const float* Wout = (const float*)d_in[2];
    const float* bout = (const float*)d_in[3];
    float* out = (float*)d_out;

    cudaFuncSetAttribute(attn_mma, cudaFuncAttributeMaxDynamicSharedMemorySize, ATTN_SMEM);

    split_x<<<4096, 256>>>(x);
    split_wT<<<dim3(96, 32), dim3(32, 8)>>>(Wqkv, 3072, 0);
    split_wT<<<dim3(32, 32), dim3(32, 8)>>>(Wout, 1024, 1);
    gemm_qkv_mma<<<dim3(24, 32), 256>>>();
    attn_mma<<<dim3(16, 32), 256, ATTN_SMEM>>>();
    gemm_out_mma<<<dim3(8, 32), 256>>>(bout, out);
}

// round 12
// speedup vs baseline: 2.0913x; 1.0781x over previous
#include <cuda_runtime.h>
#include <cuda_bf16.h>
#include <cstdint>
#include <math.h>

#define B_   2
#define H_   16
#define N_   2048
#define D_   64
#define C_   1024
#define BH_  (B_*H_)

// bf16 hi/lo scratch
__device__ __nv_bfloat16 g_xh[4096*1024], g_xl[4096*1024];     // X split, [row][k]
__device__ __nv_bfloat16 g_wqh[3072*1024], g_wql[3072*1024];   // Wqkv^T split, [n][k]
__device__ __nv_bfloat16 g_woh[1024*1024], g_wol[1024*1024];   // Wout^T split, [n][k]
__device__ __nv_bfloat16 g_aoh[4096*1024], g_aol[4096*1024];   // attn out split, [row][k]
// attention operands (written by gemm_qkv_mma epilogue)
__device__ __nv_bfloat16 g_qh2[BH_*N_*D_], g_ql2[BH_*N_*D_];   // [bh][tok][64], *log2e/32
__device__ __nv_bfloat16 g_kh2[BH_*N_*D_], g_kl2[BH_*N_*D_];   // [bh][tok][64]
__device__ __nv_bfloat16 g_vth[BH_*N_*D_], g_vtl[BH_*N_*D_];   // [bh][d][tok]  (transposed)

// ---- helpers ----
__device__ __forceinline__ uint32_t smem_u32(const void* p) {
    uint32_t a;
    asm("{ .reg .u64 t; cvta.to.shared.u64 t, %1; cvt.u32.u64 %0, t; }" : "=r"(a) : "l"(p));
    return a;
}
__device__ __forceinline__ void ldmx4(uint32_t* r, uint32_t addr) {
    asm volatile("ldmatrix.sync.aligned.m8n8.x4.shared.b16 {%0,%1,%2,%3}, [%4];"
                 : "=r"(r[0]), "=r"(r[1]), "=r"(r[2]), "=r"(r[3]) : "r"(addr));
}
__device__ __forceinline__ void mma_bf16(float* d, const uint32_t* a, uint32_t b0, uint32_t b1) {
    asm volatile("mma.sync.aligned.m16n8k16.row.col.f32.bf16.bf16.f32 "
                 "{%0,%1,%2,%3}, {%4,%5,%6,%7}, {%8,%9}, {%0,%1,%2,%3};"
                 : "+f"(d[0]), "+f"(d[1]), "+f"(d[2]), "+f"(d[3])
                 : "r"(a[0]), "r"(a[1]), "r"(a[2]), "r"(a[3]), "r"(b0), "r"(b1));
}
__device__ __forceinline__ void bsplit(float v, __nv_bfloat16& h, __nv_bfloat16& l) {
    h = __float2bfloat16_rn(v);
    l = __float2bfloat16_rn(v - __bfloat162float(h));
}
__device__ __forceinline__ uint32_t pack_bf2(__nv_bfloat16 lo, __nv_bfloat16 hi) {
    __nv_bfloat162 p; p.x = lo; p.y = hi;
    return *(uint32_t*)&p;
}
__device__ __forceinline__ void cp16(uint32_t saddr, const void* gaddr) {
    asm volatile("cp.async.cg.shared.global [%0], [%1], 16;" :: "r"(saddr), "l"(gaddr));
}
#define CP_COMMIT() asm volatile("cp.async.commit_group;" ::: "memory")
#define CP_WAIT(n)  asm volatile("cp.async.wait_group %0;" :: "n"(n) : "memory")

// ===========================================================================
// Splitters
// ===========================================================================
__global__ void __launch_bounds__(256) split_x(const float* __restrict__ X) {
    int i = blockIdx.x*256 + threadIdx.x;
    float4 v = ((const float4*)X)[i];
    __nv_bfloat16 h[4], l[4];
    bsplit(v.x, h[0], l[0]); bsplit(v.y, h[1], l[1]);
    bsplit(v.z, h[2], l[2]); bsplit(v.w, h[3], l[3]);
    *(uint2*)&g_xh[(size_t)i*4] = *(uint2*)h;
    *(uint2*)&g_xl[(size_t)i*4] = *(uint2*)l;
}

__global__ void __launch_bounds__(256) split_wT(const float* __restrict__ W, int Nn, int which) {
    __shared__ float sm[32][33];
    const int tx = threadIdx.x, ty = threadIdx.y;
    const int nx = blockIdx.x*32, kx = blockIdx.y*32;
    #pragma unroll
    for (int i = 0; i < 4; i++)
        sm[ty + i*8][tx] = W[(size_t)(kx + ty + i*8)*Nn + nx + tx];
    __syncthreads();
    __nv_bfloat16* Th = which ? g_woh : g_wqh;
    __nv_bfloat16* Tl = which ? g_wol : g_wql;
    #pragma unroll
    for (int i = 0; i < 4; i++) {
        float v = sm[tx][ty + i*8];
        __nv_bfloat16 h, l; bsplit(v, h, l);
        size_t o = (size_t)(nx + ty + i*8)*1024 + kx + tx;
        Th[o] = h; Tl[o] = l;
    }
}

// ===========================================================================
// bf16 3-pass mma GEMM, 3-stage cp.async pipeline.
// CTA 128x128, 8 warps (2m x 4n), warp 64x32. Stage = 16KB (Ah/Al/Bh/Bl 4KB).
// ===========================================================================
struct MmaCtx {
    float acc[4][4][4];
    uint32_t sb;
    int offA, offB;
    int wm, wn, lane;
    const char *gAh, *gAl, *gBh, *gBl;   // per-thread global src (byte ptrs)
    uint32_t dA;                         // per-thread smem dst cell offset (bytes)
};

__device__ __forceinline__ void mma_init(MmaCtx& c, void* smem,
        const __nv_bfloat16* Ah, const __nv_bfloat16* Al,
        const __nv_bfloat16* Bh, const __nv_bfloat16* Bl,
        int bm, int bn) {
    const int t = threadIdx.x, l = t & 31, w = t >> 5;
    c.lane = l; c.wm = w & 1; c.wn = w >> 1;
    c.sb = smem_u32(smem);
    #pragma unroll
    for (int a = 0; a < 4; a++)
        #pragma unroll
        for (int b = 0; b < 4; b++)
            #pragma unroll
            for (int d = 0; d < 4; d++) c.acc[a][b][d] = 0.f;

    const int arow = t & 127, akc = t >> 7;
    c.gAh = (const char*)(Ah + (size_t)(bm*128 + arow)*1024) + akc*16;
    c.gAl = (const char*)(Al + (size_t)(bm*128 + arow)*1024) + akc*16;
    c.gBh = (const char*)(Bh + (size_t)(bn*128 + arow)*1024) + akc*16;
    c.gBl = (const char*)(Bl + (size_t)(bn*128 + arow)*1024) + akc*16;
    c.dA = (uint32_t)((akc*128 + arow)*16);

    const int rowA = c.wm*64 + ((l>>3)&1)*8 + (l&7), kcA = l>>4;
    c.offA = (kcA*128 + rowA)*16;
    const int nB = c.wn*32 + (l&7) + (l>>4)*8, kcB = (l>>3)&1;
    c.offB = (kcB*128 + nB)*16;
}

__device__ __forceinline__ void mma_issue(MmaCtx& c, int j, int slot) {
    const uint32_t S = c.sb + slot*16384 + c.dA;
    const size_t go = (size_t)j * 32;      // 16 k-elems * 2B per stage
    cp16(S,          c.gAh + go);
    cp16(S + 4096,   c.gAl + go);
    cp16(S + 8192,   c.gBh + go);
    cp16(S + 12288,  c.gBl + go);
    CP_COMMIT();
}

__device__ __forceinline__ void mma_compute(MmaCtx& c, int slot) {
    const uint32_t S = c.sb + slot*16384;
    uint32_t Ah_[4][4], Al_[4][4];
    #pragma unroll
    for (int mt = 0; mt < 4; mt++) {
        ldmx4(Ah_[mt], S + c.offA + mt*256);
        ldmx4(Al_[mt], S + 4096 + c.offA + mt*256);
    }
    #pragma unroll
    for (int ntp = 0; ntp < 2; ntp++) {
        uint32_t bh[4], bl[4];
        ldmx4(bh, S + 8192 + c.offB + ntp*256);
        ldmx4(bl, S + 12288 + c.offB + ntp*256);
        #pragma unroll
        for (int n2 = 0; n2 < 2; n2++) {
            const int nt = ntp*2 + n2;
            #pragma unroll
            for (int mt = 0; mt < 4; mt++) {
                mma_bf16(c.acc[mt][nt], Ah_[mt], bh[n2*2], bh[n2*2+1]);
                mma_bf16(c.acc[mt][nt], Ah_[mt], bl[n2*2], bl[n2*2+1]);
                mma_bf16(c.acc[mt][nt], Al_[mt], bh[n2*2], bh[n2*2+1]);
            }
        }
    }
}

#define MMA_MAIN(c)                                        \
    mma_issue(c, 0, 0); mma_issue(c, 1, 1);                \
    for (int j = 0; j < 64; j++) {                         \
        CP_WAIT(1);                                        \
        __syncthreads();                                   \
        if (j + 2 < 64) mma_issue(c, j+2, (j+2)%3);        \
        mma_compute(c, j%3);                               \
    }

__global__ void __launch_bounds__(256, 2) gemm_qkv_mma() {
    __shared__ __align__(16) char smem[3*16384];
    MmaCtx c;
    const int bn = blockIdx.x, bm = blockIdx.y;
    mma_init(c, smem, g_xh, g_xl, g_wqh, g_wql, bm, bn);
    MMA_MAIN(c);

    const int sel = bn >> 3;
    const float sc = (sel == 0) ? 0.03125f * 1.4426950408889634f : 1.0f;
    #pragma unroll
    for (int mt = 0; mt < 4; mt++) {
        const int row0 = bm*128 + c.wm*64 + mt*16 + (c.lane >> 2);
        #pragma unroll
        for (int nt = 0; nt < 4; nt++) {
            const int col = (bn & 7)*128 + c.wn*32 + nt*8 + (c.lane & 3)*2;
            const int h = col >> 6, d = col & 63;
            #pragma unroll
            for (int half = 0; half < 2; half++) {
                const int r = row0 + half*8;
                const int bb = r >> 11, nr = r & 2047;
                const int bh_ = bb*H_ + h;
                float f0 = c.acc[mt][nt][half*2+0]*sc;
                float f1 = c.acc[mt][nt][half*2+1]*sc;
                __nv_bfloat16 h0,l0,h1,l1;
                bsplit(f0, h0, l0); bsplit(f1, h1, l1);
                if (sel == 2) {
                    size_t o = ((size_t)bh_*D_ + d)*N_ + nr;
                    g_vth[o] = h0; g_vtl[o] = l0;
                    g_vth[o + N_] = h1; g_vtl[o + N_] = l1;
                } else {
                    size_t o = ((size_t)bh_*N_ + nr)*D_ + d;
                    __nv_bfloat16* Dh = sel ? g_kh2 : g_qh2;
                    __nv_bfloat16* Dl = sel ? g_kl2 : g_ql2;
                    *(uint32_t*)&Dh[o] = pack_bf2(h0, h1);
                    *(uint32_t*)&Dl[o] = pack_bf2(l0, l1);
                }
            }
        }
    }
}

__global__ void __launch_bounds__(256, 2) gemm_out_mma(const float* __restrict__ bias,
                                                       float* __restrict__ out) {
    __shared__ __align__(16) char smem[3*16384];
    MmaCtx c;
    const int bn = blockIdx.x, bm = blockIdx.y;
    mma_init(c, smem, g_aoh, g_aol, g_woh, g_wol, bm, bn);
    MMA_MAIN(c);

    #pragma unroll
    for (int mt = 0; mt < 4; mt++) {
        const int row0 = bm*128 + c.wm*64 + mt*16 + (c.lane >> 2);
        #pragma unroll
        for (int nt = 0; nt < 4; nt++) {
            const int col = bn*128 + c.wn*32 + nt*8 + (c.lane & 3)*2;
            const float2 bv = *(const float2*)&bias[col];
            #pragma unroll
            for (int half = 0; half < 2; half++) {
                const size_t r = (size_t)(row0 + half*8);
                float2 o = make_float2(c.acc[mt][nt][half*2+0] + bv.x,
                                       c.acc[mt][nt][half*2+1] + bv.y);
                *(float2*)&out[r*C_ + col] = o;
            }
        }
    }
}

// ===========================================================================
// Attention on mma.sync, cp.async double-buffered K/V.
// smem: sQ 32KB | stage0 KV 32KB | stage1 KV 32KB  = 96KB dynamic.
// Stage: Kh@0 Kl@8192 Vh@16384 Vl@24576.
// ===========================================================================
#define ATTN_SMEM 98304

__global__ void __launch_bounds__(256) attn_mma() {
    extern __shared__ __align__(16) char smem[];
    char* sQ = smem;
    const uint32_t sbQ = smem_u32(sQ);
    const uint32_t sbKV = sbQ + 32768;

    const int t = threadIdx.x, l = t & 31, w = t >> 5;
    const int it = blockIdx.x, bh = blockIdx.y;
    const size_t base = (size_t)bh * (N_*D_);

    // Q tile -> smem [kcb][row][16B]
    {
        const int row = t & 127;
        const int kcb0 = (t >> 7) * 4;
        const uint4* gh = (const uint4*)(g_qh2 + base + (size_t)(it*128 + row)*D_);
        const uint4* gl = (const uint4*)(g_ql2 + base + (size_t)(it*128 + row)*D_);
        #pragma unroll
        for (int u = 0; u < 4; u++) {
            const int kcb = kcb0 + u;
            *(uint4*)(sQ + (kcb*128 + row)*16)         = gh[kcb];
            *(uint4*)(sQ + 16384 + (kcb*128 + row)*16) = gl[kcb];
        }
    }

    const int rowQ = w*16 + ((l>>3)&1)*8 + (l&7);
    const int offQ = rowQ*16 + (l>>4)*2048;
    const int offB = (((l>>3)&1)*64 + (l&7) + (l>>4)*8)*16;

    // K/V loader: per thread 8 x cp16 per stage
    const int jrow = t & 63;
    const int kcb2 = (t >> 6) * 2;
    const char* gKh = (const char*)(g_kh2 + base + (size_t)jrow*D_) + kcb2*16;
    const char* gKl = (const char*)(g_kl2 + base + (size_t)jrow*D_) + kcb2*16;
    const char* gVh = (const char*)(g_vth + base + (size_t)jrow*N_) + kcb2*16;
    const char* gVl = (const char*)(g_vtl + base + (size_t)jrow*N_) + kcb2*16;
    const uint32_t dK = (uint32_t)((kcb2*64 + jrow)*16);

    auto kv_issue = [&](int jt, int slot) {
        const uint32_t S = sbKV + slot*32768 + dK;
        const size_t koff = (size_t)jt * 64 * D_ * 2;   // 64 tokens * 64 k * 2B
        const size_t voff = (size_t)jt * 64 * 2;        // 64 tokens along N_, 2B
        #pragma unroll
        for (int u = 0; u < 2; u++) {
            cp16(S + u*1024,          gKh + koff + u*16);
            cp16(S + 8192 + u*1024,   gKl + koff + u*16);
            cp16(S + 16384 + u*1024,  gVh + voff + u*16);
            cp16(S + 24576 + u*1024,  gVl + voff + u*16);
        }
        CP_COMMIT();
    };

    float oacc[8][4];
    #pragma unroll
    for (int nt = 0; nt < 8; nt++)
        #pragma unroll
        for (int d = 0; d < 4; d++) oacc[nt][d] = 0.f;
    float lrun0 = 0.f, lrun1 = 0.f;

    const int row_glob0 = it*128 + w*16 + (l>>2);

    kv_issue(0, 0);

    for (int jt = 0; jt < 32; jt++) {
        CP_WAIT(0);
        __syncthreads();
        if (jt + 1 < 32) kv_issue(jt+1, (jt+1)&1);

        const uint32_t sbK = sbKV + (jt&1)*32768;
        const uint32_t sbV = sbK + 16384;

        // S = Q K^T (3-pass)
        float sacc[8][4];
        #pragma unroll
        for (int nt = 0; nt < 8; nt++)
            #pragma unroll
            for (int d = 0; d < 4; d++) sacc[nt][d] = 0.f;

        #pragma unroll
        for (int kc = 0; kc < 4; kc++) {
            uint32_t qh[4], ql[4];
            ldmx4(qh, sbQ + offQ + kc*4096);
            ldmx4(ql, sbQ + 16384 + offQ + kc*4096);
            #pragma unroll
            for (int np = 0; np < 4; np++) {
                uint32_t kbh[4], kbl[4];
                ldmx4(kbh, sbK + kc*2048 + offB + np*256);
                ldmx4(kbl, sbK + 8192 + kc*2048 + offB + np*256);
                #pragma unroll
                for (int n2 = 0; n2 < 2; n2++) {
                    const int nt = np*2 + n2;
                    mma_bf16(sacc[nt], qh, kbh[n2*2], kbh[n2*2+1]);
                    mma_bf16(sacc[nt], qh, kbl[n2*2], kbl[n2*2+1]);
                    mma_bf16(sacc[nt], ql, kbh[n2*2], kbh[n2*2+1]);
                }
            }
        }

        // mask + exp2 + partial sums + pack P into a-frags
        uint32_t pah[4][4], pal[4][4];
        #pragma unroll
        for (int nt = 0; nt < 8; nt++) {
            const int colb = jt*64 + nt*8 + (l & 3)*2;
            const int del0 = row_glob0 - colb;
            const int dels[4] = {del0, del0 - 1, del0 + 8, del0 + 7};
            float p[4];
            #pragma unroll
            for (int e = 0; e < 4; e++) {
                const int de = dels[e];
                const bool msk = (de >= 0) && ((de & 31) == 0);
                p[e] = msk ? 0.f : exp2f(sacc[nt][e]);
            }
            lrun0 += p[0] + p[1];
            lrun1 += p[2] + p[3];
            __nv_bfloat16 h0,l0,h1,l1,h2,l2,h3,l3;
            bsplit(p[0], h0, l0); bsplit(p[1], h1, l1);
            bsplit(p[2], h2, l2); bsplit(p[3], h3, l3);
            const int kk = nt >> 1, sl = (nt & 1)*2;
            pah[kk][sl+0] = pack_bf2(h0, h1);
            pah[kk][sl+1] = pack_bf2(h2, h3);
            pal[kk][sl+0] = pack_bf2(l0, l1);
            pal[kk][sl+1] = pack_bf2(l2, l3);
        }

        // O += P V (3-pass)
        #pragma unroll
        for (int kk = 0; kk < 4; kk++) {
            #pragma unroll
            for (int np = 0; np < 4; np++) {
                uint32_t vbh[4], vbl[4];
                ldmx4(vbh, sbV + kk*2048 + offB + np*256);
                ldmx4(vbl, sbV + 8192 + kk*2048 + offB + np*256);
                #pragma unroll
                for (int n2 = 0; n2 < 2; n2++) {
                    const int nt = np*2 + n2;
                    mma_bf16(oacc[nt], pah[kk], vbh[n2*2], vbh[n2*2+1]);
                    mma_bf16(oacc[nt], pah[kk], vbl[n2*2], vbl[n2*2+1]);
                    mma_bf16(oacc[nt], pal[kk], vbh[n2*2], vbh[n2*2+1]);
                }
            }
        }
    }

    // final reduce + normalize + split + store
    lrun0 += __shfl_xor_sync(0xffffffffu, lrun0, 1);
    lrun0 += __shfl_xor_sync(0xffffffffu, lrun0, 2);
    lrun1 += __shfl_xor_sync(0xffffffffu, lrun1, 1);
    lrun1 += __shfl_xor_sync(0xffffffffu, lrun1, 2);
    const float inv0 = 1.0f / lrun0, inv1 = 1.0f / lrun1;

    const int bb = bh >> 4, hh_ = bh & 15;
    #pragma unroll
    for (int nt = 0; nt < 8; nt++) {
        const int col = hh_*64 + nt*8 + (l & 3)*2;
        #pragma unroll
        for (int half = 0; half < 2; half++) {
            const float inv = half ? inv1 : inv0;
            float f0 = oacc[nt][half*2+0] * inv;
            float f1 = oacc[nt][half*2+1] * inv;
            __nv_bfloat16 h0,l0,h1,l1;
            bsplit(f0, h0, l0); bsplit(f1, h1, l1);
            const int gi = it*128 + w*16 + (l>>2) + half*8;
            const size_t o = ((size_t)bb*N_ + gi)*C_ + col;
            *(uint32_t*)&g_aoh[o] = pack_bf2(h0, h1);
            *(uint32_t*)&g_aol[o] = pack_bf2(l0, l1);
        }
    }
}

extern "C" void kernel_launch(void* const* d_in, const int* in_sizes, int n_in,
                              void* d_out, int out_size) {
    const float* x    = (const float*)d_in[0];
    const float* Wqkv = (const float*)d_in[1];
    const float* Wout = (const float*)d_in[2];
    const float* bout = (const float*)d_in[3];
    float* out = (float*)d_out;

    cudaFuncSetAttribute(attn_mma, cudaFuncAttributeMaxDynamicSharedMemorySize, ATTN_SMEM);

    split_x<<<4096, 256>>>(x);
    split_wT<<<dim3(96, 32), dim3(32, 8)>>>(Wqkv, 3072, 0);
    split_wT<<<dim3(32, 32), dim3(32, 8)>>>(Wout, 1024, 1);
    gemm_qkv_mma<<<dim3(24, 32), 256>>>();
    attn_mma<<<dim3(16, 32), 256, ATTN_SMEM>>>();
    gemm_out_mma<<<dim3(8, 32), 256>>>(bout, out);
}